// round 6
// baseline (speedup 1.0000x reference)
#include <cuda_runtime.h>
#include <cstdint>

// MXFP (EXP_W=2, MAN_W=1, GROUP=32) quantize-dequantize, fp32 -> fp32.
// Grid magnitudes: 0, {0.5,0.75,1,1.5,2,3,4,6} * scale, scale = 2^(floor(log2 max|g|)-2).
// Persistent grid-stride kernel: one wave, MLP_p1=2 per iteration.

__device__ __forceinline__ float pow2i(int k) {
    // exact 2^k for k in [-126,127]
    return __uint_as_float((uint32_t)(k + 127) << 23);
}

// Quantize one element. inv = 2^-pot, sc2 = 2^(pot+1); both pow2-exact.
__device__ __forceinline__ float q_elem(float v, float inv, float sc2) {
    const float C22 = 4194304.0f;                 // 2^22
    float a = __fmul_rn(fabsf(v), inv);           // exact; a in [0,8)
    // RNE snap to 1-mantissa-bit grid 2^(e-1): c = a*2^22 exact
    float r = __fmaf_rn(a, C22, a);               // t = a + c
    r = __fmaf_rn(a, -C22, r);                    // r = t - c  (exact)
    r = fminf(fmaxf(r, 0.5f), 6.0f);              // clamp to [min_repr, max_repr]
    // zero-mask: s = RN(a + 2^22) - 2^22 rounds a half-even to multiples of
    // 0.5; s == 0 iff a <= 0.25 (tie at 0.25 -> even -> 0), else s >= 0.5.
    float s = __fadd_rn(a, C22);
    s = __fsub_rn(s, C22);
    float m = fminf(s, 0.5f);                     // 0 or 0.5
    return copysignf(__fmul_rn(__fmul_rn(r, m), sc2), v);
}

__device__ __forceinline__ float4 qtile(float4 v, float inv, float sc2) {
    float4 o;
    o.x = q_elem(v.x, inv, sc2);
    o.y = q_elem(v.y, inv, sc2);
    o.z = q_elem(v.z, inv, sc2);
    o.w = q_elem(v.w, inv, sc2);
    return o;
}

__global__ void __launch_bounds__(256, 8)
mxfp_quant_kernel(const float4* __restrict__ x, float4* __restrict__ y, int n4) {
    const int stride = gridDim.x * 512;
    // n4 is a multiple of 512 for this problem, so if base is in range the
    // whole 512-float4 block tile is in range.
    for (int base = blockIdx.x * 512 + threadIdx.x; base < n4; base += stride) {
        float4 v0 = __ldcs(x + base);
        float4 v1 = __ldcs(x + base + 256);

        // per-thread max of 4 (abs folds into FMNMX modifiers)
        float m0 = fmaxf(fmaxf(fabsf(v0.x), fabsf(v0.y)), fmaxf(fabsf(v0.z), fabsf(v0.w)));
        float m1 = fmaxf(fmaxf(fabsf(v1.x), fabsf(v1.y)), fmaxf(fabsf(v1.z), fabsf(v1.w)));

        // 8-lane octet reduction = one 32-elem group per tile
        m0 = fmaxf(m0, __shfl_xor_sync(0xffffffffu, m0, 1));
        m1 = fmaxf(m1, __shfl_xor_sync(0xffffffffu, m1, 1));
        m0 = fmaxf(m0, __shfl_xor_sync(0xffffffffu, m0, 2));
        m1 = fmaxf(m1, __shfl_xor_sync(0xffffffffu, m1, 2));
        m0 = fmaxf(m0, __shfl_xor_sync(0xffffffffu, m0, 4));
        m1 = fmaxf(m1, __shfl_xor_sync(0xffffffffu, m1, 4));

        // pot = clip(floor(log2 m) - 2, -127, ...): biased-exp trick; m==0 or
        // subnormal clips to -127 (all-zero groups are zeroed by the mask,
        // matching the reference's m->1 branch).
        int p0 = max((int)(__float_as_uint(m0) >> 23) - 129, -127);
        int p1 = max((int)(__float_as_uint(m1) >> 23) - 129, -127);

        // inv = 2^-pot, sc2 = 2^(pot+1); normal-range exact (pot in [-127,125])
        __stcs(y + base,       qtile(v0, pow2i(-p0), pow2i(p0 + 1)));
        __stcs(y + base + 256, qtile(v1, pow2i(-p1), pow2i(p1 + 1)));
    }
}

extern "C" void kernel_launch(void* const* d_in, const int* in_sizes, int n_in,
                              void* d_out, int out_size) {
    const float4* x = (const float4*)d_in[0];
    float4* y = (float4*)d_out;
    int n = in_sizes[0];           // 33,554,432
    int n4 = n >> 2;               // 8,388,608 float4s (multiple of 512)

    int sms = 148;
    cudaDeviceGetAttribute(&sms, cudaDevAttrMultiProcessorCount, 0);
    int blocks = sms * 8;          // one full wave at occupancy 8
    int tiles = n4 / 512;
    if (blocks > tiles) blocks = tiles;

    mxfp_quant_kernel<<<blocks, 256>>>(x, y, n4);
}

// round 7
// speedup vs baseline: 1.0629x; 1.0629x over previous
#include <cuda_runtime.h>
#include <cstdint>

// MXFP (EXP_W=2, MAN_W=1, GROUP=32) quantize-dequantize, fp32 -> fp32.
// Grid magnitudes: 0, {0.5,0.75,1,1.5,2,3,4,6} * scale, scale = 2^(floor(log2 max|g|)-2).
// Shape: R2's best-measured launch (grid-launched, MLP_p1=2, default cache ops)
// + cheap FMA-pipe element math (bit-identical to reference).

__device__ __forceinline__ float pow2i(int k) {
    // exact 2^k for k in [-126,127]
    return __uint_as_float((uint32_t)(k + 127) << 23);
}

// Quantize one element. inv = 2^-pot, sc2 = 2^(pot+1); both pow2-exact.
__device__ __forceinline__ float q_elem(float v, float inv, float sc2) {
    const float C22 = 4194304.0f;                 // 2^22
    float a = __fmul_rn(fabsf(v), inv);           // exact; a in [0,8)
    // RNE snap to 1-mantissa-bit grid 2^(e-1): c = a*2^22 exact
    float r = __fmaf_rn(a, C22, a);               // t = a + c
    r = __fmaf_rn(a, -C22, r);                    // r = t - c  (exact)
    r = fminf(fmaxf(r, 0.5f), 6.0f);              // clamp to [min_repr, max_repr]
    // zero-mask: s = RN(a + 2^22) - 2^22 rounds a half-even to multiples of
    // 0.5; s == 0 iff a <= 0.25 (tie at 0.25 -> even -> 0), else s >= 0.5.
    float s = __fadd_rn(a, C22);
    s = __fsub_rn(s, C22);
    float m = fminf(s, 0.5f);                     // 0 or 0.5
    return copysignf(__fmul_rn(__fmul_rn(r, m), sc2), v);
}

__device__ __forceinline__ float4 qtile(float4 v, float inv, float sc2) {
    float4 o;
    o.x = q_elem(v.x, inv, sc2);
    o.y = q_elem(v.y, inv, sc2);
    o.z = q_elem(v.z, inv, sc2);
    o.w = q_elem(v.w, inv, sc2);
    return o;
}

__global__ void __launch_bounds__(256, 8)
mxfp_quant_kernel(const float4* __restrict__ x, float4* __restrict__ y) {
    int base = blockIdx.x * 512 + threadIdx.x;    // two tiles of 256 float4s
    int i1 = base + 256;

    float4 v0 = x[base];
    float4 v1 = x[i1];

    // per-thread max of 4 (abs folds into FMNMX modifiers), two chains
    float m0 = fmaxf(fmaxf(fabsf(v0.x), fabsf(v0.y)), fmaxf(fabsf(v0.z), fabsf(v0.w)));
    float m1 = fmaxf(fmaxf(fabsf(v1.x), fabsf(v1.y)), fmaxf(fabsf(v1.z), fabsf(v1.w)));

    // 8-lane octet reduction = one 32-elem group per tile (interleaved ILP)
    m0 = fmaxf(m0, __shfl_xor_sync(0xffffffffu, m0, 1));
    m1 = fmaxf(m1, __shfl_xor_sync(0xffffffffu, m1, 1));
    m0 = fmaxf(m0, __shfl_xor_sync(0xffffffffu, m0, 2));
    m1 = fmaxf(m1, __shfl_xor_sync(0xffffffffu, m1, 2));
    m0 = fmaxf(m0, __shfl_xor_sync(0xffffffffu, m0, 4));
    m1 = fmaxf(m1, __shfl_xor_sync(0xffffffffu, m1, 4));

    // pot = clip(floor(log2 m) - 2, -127, ...): biased-exp trick; m==0 or
    // subnormal clips to -127 (all-zero groups are zeroed by the mask,
    // matching the reference's m->1 branch).
    int p0 = max((int)(__float_as_uint(m0) >> 23) - 129, -127);
    int p1 = max((int)(__float_as_uint(m1) >> 23) - 129, -127);

    // inv = 2^-pot, sc2 = 2^(pot+1); normal-range exact (pot in [-127,125])
    y[base] = qtile(v0, pow2i(-p0), pow2i(p0 + 1));
    y[i1]   = qtile(v1, pow2i(-p1), pow2i(p1 + 1));
}

extern "C" void kernel_launch(void* const* d_in, const int* in_sizes, int n_in,
                              void* d_out, int out_size) {
    const float4* x = (const float4*)d_in[0];
    float4* y = (float4*)d_out;
    int n = in_sizes[0];                 // 33,554,432 = 16384 * 512 * 4
    int n4 = n >> 2;
    int blocks = n4 / 512;               // exact for this shape: 16384
    mxfp_quant_kernel<<<blocks, 256>>>(x, y);
}

// round 11
// speedup vs baseline: 1.0949x; 1.0302x over previous
#include <cuda_runtime.h>
#include <cstdint>

// MXFP (EXP_W=2, MAN_W=1, GROUP=32) quantize-dequantize, fp32 -> fp32.
// Grid magnitudes: 0, {0.5,0.75,1,1.5,2,3,4,6} * scale, scale = 2^(floor(log2 max|g|)-2).
// R2 launch shape (grid-launched, 2 tiles/thread, default cache ops)
// + single REDUX.SYNC octet max (abs floats: uint order == float order)
// + FMA-pipe element math (bit-identical to reference).

__device__ __forceinline__ float pow2i(int k) {
    // exact 2^k for k in [-126,127]
    return __uint_as_float((uint32_t)(k + 127) << 23);
}

// Quantize one element. inv = 2^-pot, sc2 = 2^(pot+1); both pow2-exact.
__device__ __forceinline__ float q_elem(float v, float inv, float sc2) {
    const float C22 = 4194304.0f;                 // 2^22
    float a = __fmul_rn(fabsf(v), inv);           // exact; a in [0,8)
    // RNE snap to 1-mantissa-bit grid 2^(e-1): c = a*2^22 exact
    float r = __fmaf_rn(a, C22, a);               // t = a + c
    r = __fmaf_rn(a, -C22, r);                    // r = t - c  (exact)
    r = fminf(fmaxf(r, 0.5f), 6.0f);              // clamp to [min_repr, max_repr]
    // zero-mask: s = RN(a + 2^22) - 2^22 rounds a half-even to multiples of
    // 0.5; s == 0 iff a <= 0.25 (tie at 0.25 -> even -> 0), else s >= 0.5.
    float s = __fadd_rn(a, C22);
    s = __fsub_rn(s, C22);
    float m = fminf(s, 0.5f);                     // 0 or 0.5
    return copysignf(__fmul_rn(__fmul_rn(r, m), sc2), v);
}

__device__ __forceinline__ float4 qtile(float4 v, float inv, float sc2) {
    float4 o;
    o.x = q_elem(v.x, inv, sc2);
    o.y = q_elem(v.y, inv, sc2);
    o.z = q_elem(v.z, inv, sc2);
    o.w = q_elem(v.w, inv, sc2);
    return o;
}

__global__ void __launch_bounds__(256, 8)
mxfp_quant_kernel(const float4* __restrict__ x, float4* __restrict__ y) {
    int base = blockIdx.x * 512 + threadIdx.x;    // two tiles of 256 float4s
    int i1 = base + 256;

    float4 v0 = x[base];
    float4 v1 = x[i1];

    // per-thread max of 4 (abs folds into FMNMX modifiers), two chains
    float m0 = fmaxf(fmaxf(fabsf(v0.x), fabsf(v0.y)), fmaxf(fabsf(v0.z), fabsf(v0.w)));
    float m1 = fmaxf(fmaxf(fabsf(v1.x), fabsf(v1.y)), fmaxf(fabsf(v1.z), fabsf(v1.w)));

    // Octet (8-lane = one 32-elem group) max in ONE redux each: values are
    // non-negative, so unsigned-int order == float order on the bit patterns.
    unsigned lane = threadIdx.x & 31u;
    unsigned omask = 0xFFu << (lane & 24u);       // disjoint per-octet masks
    unsigned b0 = __reduce_max_sync(omask, __float_as_uint(m0));
    unsigned b1 = __reduce_max_sync(omask, __float_as_uint(m1));

    // pot = clip(floor(log2 m) - 2, -127, ...): biased-exp trick; m==0 or
    // subnormal clips to -127 (all-zero groups are zeroed by the mask,
    // matching the reference's m->1 branch).
    int p0 = max((int)(b0 >> 23) - 129, -127);
    int p1 = max((int)(b1 >> 23) - 129, -127);

    // inv = 2^-pot, sc2 = 2^(pot+1); normal-range exact (pot in [-127,125])
    y[base] = qtile(v0, pow2i(-p0), pow2i(p0 + 1));
    y[i1]   = qtile(v1, pow2i(-p1), pow2i(p1 + 1));
}

extern "C" void kernel_launch(void* const* d_in, const int* in_sizes, int n_in,
                              void* d_out, int out_size) {
    const float4* x = (const float4*)d_in[0];
    float4* y = (float4*)d_out;
    int n = in_sizes[0];                 // 33,554,432 = 16384 * 512 * 4
    int n4 = n >> 2;
    int blocks = n4 / 512;               // exact for this shape: 16384
    mxfp_quant_kernel<<<blocks, 256>>>(x, y);
}